// round 1
// baseline (speedup 1.0000x reference)
#include <cuda_runtime.h>
#include <math.h>

#define NMAX 50000
#define MMAX 800000
#define DD 256

// ---------------- scratch (static device globals; no allocation) ----------------
__device__ __align__(16) float g_Q[(size_t)NMAX * DD];
__device__ __align__(16) float g_K[(size_t)NMAX * DD];
__device__ __align__(16) float g_V[(size_t)NMAX * DD];
__device__ __align__(16) float g_att[(size_t)MMAX * 8];   // qk logits, then exp'd att (in place)
__device__ __align__(16) float g_sums[(size_t)NMAX * 8];  // segment sums per (node, head)
__device__ __align__(16) float g_agg[(size_t)NMAX * DD];  // scatter-add target
__device__ __align__(16) float g_h1[(size_t)NMAX * DD];   // hidden after Wagg
__device__ int   g_maxbits;                                // ordered-int encoded global max of qk
__device__ float g_scale;                                  // 3.0f / max(qk)

// ordered-int encoding for float atomicMax (handles negatives)
__device__ __forceinline__ int f2ord(float f) {
    int b = __float_as_int(f);
    return b >= 0 ? b : (b ^ 0x7FFFFFFF);
}

// ---------------- init: zero accumulators, reset max ----------------
__global__ void init_kernel(int n4_agg, int n4_sums) {
    int i = blockIdx.x * blockDim.x + threadIdx.x;
    float4 z = make_float4(0.f, 0.f, 0.f, 0.f);
    if (i < n4_agg)  ((float4*)g_agg)[i]  = z;
    if (i < n4_sums) ((float4*)g_sums)[i] = z;
    if (i == 0) g_maxbits = 0x80000000;  // below any finite encoding
}

// ---------------- fp32 GEMM: C[n,0:256] = act(actin(A[n,:]) @ W + b) (+x) ----------------
// A: (nrows,256) row-major, W: (256,256) row-major, bias: (256)
// tiles: BM=128, BN=64, BK=32; 256 threads; 8x4 per-thread microtile
template<bool RELU_IN, bool RELU_OUT, bool ADD_RES>
__global__ __launch_bounds__(256)
void gemm256(const float* __restrict__ A, const float* __restrict__ W,
             const float* __restrict__ bias, float* __restrict__ C,
             const float* __restrict__ res, int nrows)
{
    __shared__ __align__(16) float As[32 * 132];  // [k][m], padded stride 132
    __shared__ __align__(16) float Ws[32 * 64];   // [k][n]

    const int tid = threadIdx.x;
    const int m0 = blockIdx.x * 128;
    const int n0 = blockIdx.y * 64;
    const int tx = tid & 15;    // n: 16 x 4
    const int ty = tid >> 4;    // m: 16 x 8
    const int arow = tid >> 3;  // 0..31
    const int akv  = tid & 7;   // 0..7

    float acc[8][4];
#pragma unroll
    for (int i = 0; i < 8; i++)
#pragma unroll
        for (int j = 0; j < 4; j++) acc[i][j] = 0.f;

#pragma unroll 1
    for (int kt = 0; kt < 8; ++kt) {
        const int k0 = kt * 32;
        // load A tile 128x32 (transposed into As[k][m])
#pragma unroll
        for (int it = 0; it < 4; ++it) {
            int row = it * 32 + arow;
            int gm = m0 + row;
            float4 v = make_float4(0.f, 0.f, 0.f, 0.f);
            if (gm < nrows) v = *(const float4*)(A + (size_t)gm * 256 + k0 + akv * 4);
            if (RELU_IN) {
                v.x = fmaxf(v.x, 0.f); v.y = fmaxf(v.y, 0.f);
                v.z = fmaxf(v.z, 0.f); v.w = fmaxf(v.w, 0.f);
            }
            As[(akv * 4 + 0) * 132 + row] = v.x;
            As[(akv * 4 + 1) * 132 + row] = v.y;
            As[(akv * 4 + 2) * 132 + row] = v.z;
            As[(akv * 4 + 3) * 132 + row] = v.w;
        }
        // load W tile 32x64
#pragma unroll
        for (int it = 0; it < 2; ++it) {
            int idx = it * 256 + tid;  // 0..511
            int kr = idx >> 4;
            int nv = idx & 15;
            float4 v = *(const float4*)(W + (size_t)(k0 + kr) * 256 + n0 + nv * 4);
            *(float4*)(Ws + kr * 64 + nv * 4) = v;
        }
        __syncthreads();
#pragma unroll
        for (int k = 0; k < 32; ++k) {
            float4 a0 = *(const float4*)(As + k * 132 + ty * 8);
            float4 a1 = *(const float4*)(As + k * 132 + ty * 8 + 4);
            float4 w  = *(const float4*)(Ws + k * 64 + tx * 4);
            float am[8] = {a0.x, a0.y, a0.z, a0.w, a1.x, a1.y, a1.z, a1.w};
            float wn[4] = {w.x, w.y, w.z, w.w};
#pragma unroll
            for (int i = 0; i < 8; i++)
#pragma unroll
                for (int j = 0; j < 4; j++)
                    acc[i][j] = fmaf(am[i], wn[j], acc[i][j]);
        }
        __syncthreads();
    }

    float4 b = *(const float4*)(bias + n0 + tx * 4);
#pragma unroll
    for (int i = 0; i < 8; i++) {
        int gm = m0 + ty * 8 + i;
        if (gm < nrows) {
            float4 o;
            o.x = acc[i][0] + b.x; o.y = acc[i][1] + b.y;
            o.z = acc[i][2] + b.z; o.w = acc[i][3] + b.w;
            if (RELU_OUT) {
                o.x = fmaxf(o.x, 0.f); o.y = fmaxf(o.y, 0.f);
                o.z = fmaxf(o.z, 0.f); o.w = fmaxf(o.w, 0.f);
            }
            if (ADD_RES) {
                float4 r = *(const float4*)(res + (size_t)gm * 256 + n0 + tx * 4);
                o.x += r.x; o.y += r.y; o.z += r.z; o.w += r.w;
            }
            *(float4*)(C + (size_t)gm * 256 + n0 + tx * 4) = o;
        }
    }
}

// ---------------- edge qk: one warp per edge; 8 per-head dot32 + global max ----------------
__global__ __launch_bounds__(256)
void edge_qk(const int* __restrict__ recv, const int* __restrict__ send, int m)
{
    __shared__ int smax;
    if (threadIdx.x == 0) smax = 0x80000000;
    __syncthreads();

    const int w = (blockIdx.x * blockDim.x + threadIdx.x) >> 5;
    const int lane = threadIdx.x & 31;
    if (w < m) {
        const int r = recv[w];
        const int s = send[w];
        const float4* Q4 = (const float4*)(g_Q + (size_t)r * 256);
        const float4* K4 = (const float4*)(g_K + (size_t)s * 256);
        // float4 idx f covers head f>>3; each lane handles f=lane and f=lane+32
        float4 qa = Q4[lane],       ka = K4[lane];
        float4 qb = Q4[lane + 32],  kb = K4[lane + 32];
        float s0 = qa.x * ka.x + qa.y * ka.y + qa.z * ka.z + qa.w * ka.w;
        float s1 = qb.x * kb.x + qb.y * kb.y + qb.z * kb.z + qb.w * kb.w;
        // reduce within 8-lane groups (one group per head pair)
#pragma unroll
        for (int off = 4; off; off >>= 1) {
            s0 += __shfl_xor_sync(0xffffffffu, s0, off);
            s1 += __shfl_xor_sync(0xffffffffu, s1, off);
        }
        if ((lane & 7) == 0) {
            int g = lane >> 3;                       // heads g and g+4
            g_att[(size_t)w * 8 + g]     = s0;
            g_att[(size_t)w * 8 + g + 4] = s1;
            atomicMax(&smax, f2ord(fmaxf(s0, s1)));
        }
    }
    __syncthreads();
    if (threadIdx.x == 0) atomicMax(&g_maxbits, smax);
}

// ---------------- tiny: decode max, compute scale ----------------
__global__ void scale_kernel() {
    int b = g_maxbits;
    float mx = __int_as_float(b >= 0 ? b : (b ^ 0x7FFFFFFF));
    g_scale = 3.0f / mx;
}

// ---------------- exp + segment-sum scatter (thread per edge-head) ----------------
__global__ __launch_bounds__(256)
void edge_exp(const int* __restrict__ recv, int m)
{
    int tid = blockIdx.x * blockDim.x + threadIdx.x;
    if (tid >= m * 8) return;
    int e = tid >> 3;
    int h = tid & 7;
    float a = expf(g_att[tid] * g_scale);
    g_att[tid] = a;
    atomicAdd(&g_sums[(size_t)recv[e] * 8 + h], a);
}

// ---------------- weighted message scatter: warp per edge, vector red.v4 ----------------
__device__ __forceinline__ void red_add_v4(float* p, float4 v) {
    asm volatile("red.global.add.v4.f32 [%0], {%1,%2,%3,%4};"
                 :: "l"(p), "f"(v.x), "f"(v.y), "f"(v.z), "f"(v.w) : "memory");
}

__global__ __launch_bounds__(256)
void edge_msg(const int* __restrict__ recv, const int* __restrict__ send, int m)
{
    const int w = (blockIdx.x * blockDim.x + threadIdx.x) >> 5;
    const int lane = threadIdx.x & 31;
    if (w >= m) return;
    const int r = recv[w];
    const int s = send[w];
    float wv = 0.f;
    if (lane < 8) {
        float a = g_att[(size_t)w * 8 + lane];
        float d = g_sums[(size_t)r * 8 + lane];
        wv = a / (d * 5.656854249492381f);  // sqrt(DK)=sqrt(32)
    }
    const float4* V4 = (const float4*)(g_V + (size_t)s * 256);
    float*        Ar = g_agg + (size_t)r * 256;

    float w0 = __shfl_sync(0xffffffffu, wv, lane >> 3);
    float w1 = __shfl_sync(0xffffffffu, wv, (lane + 32) >> 3);
    float4 v0 = V4[lane];
    float4 v1 = V4[lane + 32];
    v0.x *= w0; v0.y *= w0; v0.z *= w0; v0.w *= w0;
    v1.x *= w1; v1.y *= w1; v1.z *= w1; v1.w *= w1;
    red_add_v4(Ar + lane * 4, v0);
    red_add_v4(Ar + (lane + 32) * 4, v1);
}

// ---------------- launch ----------------
extern "C" void kernel_launch(void* const* d_in, const int* in_sizes, int n_in,
                              void* d_out, int out_size)
{
    const float* x    = (const float*)d_in[0];
    const int*   ei   = (const int*)d_in[1];
    const float* Wk   = (const float*)d_in[2];
    const float* bk   = (const float*)d_in[3];
    const float* Wq   = (const float*)d_in[4];
    const float* bq   = (const float*)d_in[5];
    const float* Wv   = (const float*)d_in[6];
    const float* bv   = (const float*)d_in[7];
    const float* Wagg = (const float*)d_in[8];
    const float* bagg = (const float*)d_in[9];
    const float* Wff  = (const float*)d_in[10];
    const float* bff  = (const float*)d_in[11];
    float* out = (float*)d_out;

    const int n = in_sizes[0] / 256;
    const int m = in_sizes[1] / 2;
    const int* recv = ei;
    const int* send = ei + m;

    float *Qp, *Kp, *Vp, *aggp, *h1p;
    cudaGetSymbolAddress((void**)&Qp,   g_Q);
    cudaGetSymbolAddress((void**)&Kp,   g_K);
    cudaGetSymbolAddress((void**)&Vp,   g_V);
    cudaGetSymbolAddress((void**)&aggp, g_agg);
    cudaGetSymbolAddress((void**)&h1p,  g_h1);

    const int n4_agg  = n * 64;  // float4 count of g_agg
    const int n4_sums = n * 2;   // float4 count of g_sums
    init_kernel<<<(n4_agg + 255) / 256, 256>>>(n4_agg, n4_sums);

    dim3 gg((n + 127) / 128, 4);
    gemm256<false, false, false><<<gg, 256>>>(x, Wq, bq, Qp, nullptr, n);
    gemm256<false, false, false><<<gg, 256>>>(x, Wk, bk, Kp, nullptr, n);
    gemm256<false, false, false><<<gg, 256>>>(x, Wv, bv, Vp, nullptr, n);

    edge_qk<<<(m + 7) / 8, 256>>>(recv, send, m);
    scale_kernel<<<1, 1>>>();
    edge_exp<<<(m * 8 + 255) / 256, 256>>>(recv, m);
    edge_msg<<<(m + 7) / 8, 256>>>(recv, send, m);

    gemm256<true,  true,  false><<<gg, 256>>>(aggp, Wagg, bagg, h1p, nullptr, n);
    gemm256<false, true,  true ><<<gg, 256>>>(h1p,  Wff,  bff,  out, x,       n);
}

// round 3
// speedup vs baseline: 1.7578x; 1.7578x over previous
#include <cuda_runtime.h>
#include <math.h>

#define NMAX 50000
#define MMAX 800000
#define DD 256

// ---------------- scratch (static device globals; no allocation) ----------------
__device__ __align__(16) float g_Q[(size_t)NMAX * DD];
__device__ __align__(16) float g_K[(size_t)NMAX * DD];
__device__ __align__(16) float g_V[(size_t)NMAX * DD];
__device__ __align__(16) float g_att[(size_t)MMAX * 8];   // qk logits, then exp'd att (in place)
__device__ __align__(16) float g_sums[(size_t)NMAX * 8];  // segment sums per (node, head)
__device__ __align__(16) float g_agg[(size_t)NMAX * DD];  // scatter-add target
__device__ __align__(16) float g_h1[(size_t)NMAX * DD];   // hidden after Wagg
__device__ int   g_maxbits;
__device__ float g_scale;

__device__ __forceinline__ int f2ord(float f) {
    int b = __float_as_int(f);
    return b >= 0 ? b : (b ^ 0x7FFFFFFF);
}

__device__ __forceinline__ unsigned f2tf32(float f) {
    unsigned u;
    asm("cvt.rna.tf32.f32 %0, %1;" : "=r"(u) : "f"(f));
    return u;
}

__device__ __forceinline__ void mma_tf32(float* c, unsigned a0, unsigned a1,
                                         unsigned a2, unsigned a3,
                                         unsigned b0, unsigned b1) {
    asm volatile(
        "mma.sync.aligned.m16n8k8.row.col.f32.tf32.tf32.f32 "
        "{%0,%1,%2,%3}, {%4,%5,%6,%7}, {%8,%9}, {%0,%1,%2,%3};"
        : "+f"(c[0]), "+f"(c[1]), "+f"(c[2]), "+f"(c[3])
        : "r"(a0), "r"(a1), "r"(a2), "r"(a3), "r"(b0), "r"(b1));
}

// ---------------- init ----------------
__global__ void init_kernel(int n4_agg, int n4_sums) {
    int i = blockIdx.x * blockDim.x + threadIdx.x;
    float4 z = make_float4(0.f, 0.f, 0.f, 0.f);
    if (i < n4_agg)  ((float4*)g_agg)[i]  = z;
    if (i < n4_sums) ((float4*)g_sums)[i] = z;
    if (i == 0) g_maxbits = 0x80000000;
}

// ---------------- TF32 tensor-core GEMM ----------------
// C (nrows x 256) = act( actin(A) @ W + b ) [+ res]
// Block tile 128(m) x 128(n), BK=32. 8 warps: 2(m) x 4(n), warp tile 64x32.
// grid.z selects among up to 3 weight/bias/output sets (fused QKV).
struct GemmSet { const float* W; const float* b; float* C; };

#define AS_STRIDE 36   // [m=128][k=32+4pad]  -> bank(4m+k): conflict-free frags
#define WS_STRIDE 136  // [k=32][n=128+8pad]  -> bank(8k+n): conflict-free frags

template<bool RELU_IN, bool RELU_OUT, bool ADD_RES>
__global__ __launch_bounds__(256)
void gemm_tc(const float* __restrict__ A,
             GemmSet s0, GemmSet s1, GemmSet s2,
             const float* __restrict__ res, int nrows)
{
    __shared__ __align__(16) unsigned As[128 * AS_STRIDE];
    __shared__ __align__(16) unsigned Ws[32 * WS_STRIDE];

    const GemmSet gs = (blockIdx.z == 0) ? s0 : (blockIdx.z == 1) ? s1 : s2;
    const float* __restrict__ W    = gs.W;
    const float* __restrict__ bias = gs.b;
    float* __restrict__ C          = gs.C;

    const int tid  = threadIdx.x;
    const int lane = tid & 31;
    const int warp = tid >> 5;
    const int wm   = warp >> 2;          // 0..1
    const int wn   = warp & 3;           // 0..3
    const int m0   = blockIdx.x * 128;
    const int n0   = blockIdx.y * 128;

    float acc[4][4][4];
#pragma unroll
    for (int i = 0; i < 4; i++)
#pragma unroll
        for (int j = 0; j < 4; j++)
#pragma unroll
            for (int k = 0; k < 4; k++) acc[i][j][k] = 0.f;

#pragma unroll 1
    for (int kt = 0; kt < 8; ++kt) {
        const int k0 = kt * 32;

        // A tile: 128 rows x 32 k = 1024 float4 loads (4 iters x 256 threads)
#pragma unroll
        for (int it = 0; it < 4; ++it) {
            int idx = it * 256 + tid;
            int row = idx >> 3;
            int kv  = idx & 7;
            int gm  = m0 + row;
            float4 v = make_float4(0.f, 0.f, 0.f, 0.f);
            if (gm < nrows) v = *(const float4*)(A + (size_t)gm * 256 + k0 + kv * 4);
            if (RELU_IN) {
                v.x = fmaxf(v.x, 0.f); v.y = fmaxf(v.y, 0.f);
                v.z = fmaxf(v.z, 0.f); v.w = fmaxf(v.w, 0.f);
            }
            uint4 u = make_uint4(f2tf32(v.x), f2tf32(v.y), f2tf32(v.z), f2tf32(v.w));
            *(uint4*)(As + row * AS_STRIDE + kv * 4) = u;
        }
        // W tile: 32 k x 128 n = 1024 float4 loads (4 iters x 256 threads)
#pragma unroll
        for (int it = 0; it < 4; ++it) {
            int idx = it * 256 + tid;       // 0..1023
            int kr  = idx >> 5;             // 0..31
            int nv  = idx & 31;             // 0..31
            float4 v = *(const float4*)(W + (size_t)(k0 + kr) * 256 + n0 + nv * 4);
            uint4 u = make_uint4(f2tf32(v.x), f2tf32(v.y), f2tf32(v.z), f2tf32(v.w));
            *(uint4*)(Ws + kr * WS_STRIDE + nv * 4) = u;
        }
        __syncthreads();

#pragma unroll
        for (int ks = 0; ks < 4; ++ks) {
            const int kk = ks * 8;
            unsigned af[4][4];
#pragma unroll
            for (int mt = 0; mt < 4; ++mt) {
                int r = wm * 64 + mt * 16 + (lane >> 2);
                int kc = kk + (lane & 3);
                af[mt][0] = As[r * AS_STRIDE + kc];
                af[mt][1] = As[(r + 8) * AS_STRIDE + kc];
                af[mt][2] = As[r * AS_STRIDE + kc + 4];
                af[mt][3] = As[(r + 8) * AS_STRIDE + kc + 4];
            }
            unsigned bf[4][2];
#pragma unroll
            for (int nt = 0; nt < 4; ++nt) {
                int n = wn * 32 + nt * 8 + (lane >> 2);
                bf[nt][0] = Ws[(kk + (lane & 3)) * WS_STRIDE + n];
                bf[nt][1] = Ws[(kk + 4 + (lane & 3)) * WS_STRIDE + n];
            }
#pragma unroll
            for (int mt = 0; mt < 4; ++mt)
#pragma unroll
                for (int nt = 0; nt < 4; ++nt)
                    mma_tf32(acc[mt][nt], af[mt][0], af[mt][1], af[mt][2], af[mt][3],
                             bf[nt][0], bf[nt][1]);
        }
        __syncthreads();
    }

    // epilogue
#pragma unroll
    for (int mt = 0; mt < 4; ++mt) {
#pragma unroll
        for (int nt = 0; nt < 4; ++nt) {
            int c  = n0 + wn * 32 + nt * 8 + 2 * (lane & 3);
            float2 b = *(const float2*)(bias + c);
            int r0 = m0 + wm * 64 + mt * 16 + (lane >> 2);
#pragma unroll
            for (int h = 0; h < 2; ++h) {
                int gm = r0 + h * 8;
                if (gm < nrows) {
                    float2 o;
                    o.x = acc[mt][nt][h * 2 + 0] + b.x;
                    o.y = acc[mt][nt][h * 2 + 1] + b.y;
                    if (RELU_OUT) { o.x = fmaxf(o.x, 0.f); o.y = fmaxf(o.y, 0.f); }
                    if (ADD_RES) {
                        float2 r = *(const float2*)(res + (size_t)gm * 256 + c);
                        o.x += r.x; o.y += r.y;
                    }
                    *(float2*)(C + (size_t)gm * 256 + c) = o;
                }
            }
        }
    }
}

// ---------------- edge qk: one warp per edge ----------------
__global__ __launch_bounds__(256)
void edge_qk(const int* __restrict__ recv, const int* __restrict__ send, int m)
{
    __shared__ int smax;
    if (threadIdx.x == 0) smax = 0x80000000;
    __syncthreads();

    const int w = (blockIdx.x * blockDim.x + threadIdx.x) >> 5;
    const int lane = threadIdx.x & 31;
    if (w < m) {
        const int r = recv[w];
        const int s = send[w];
        const float4* Q4 = (const float4*)(g_Q + (size_t)r * 256);
        const float4* K4 = (const float4*)(g_K + (size_t)s * 256);
        float4 qa = Q4[lane],      ka = K4[lane];
        float4 qb = Q4[lane + 32], kb = K4[lane + 32];
        float s0 = qa.x * ka.x + qa.y * ka.y + qa.z * ka.z + qa.w * ka.w;
        float s1 = qb.x * kb.x + qb.y * kb.y + qb.z * kb.z + qb.w * kb.w;
#pragma unroll
        for (int off = 4; off; off >>= 1) {
            s0 += __shfl_xor_sync(0xffffffffu, s0, off);
            s1 += __shfl_xor_sync(0xffffffffu, s1, off);
        }
        if ((lane & 7) == 0) {
            int g = lane >> 3;
            g_att[(size_t)w * 8 + g]     = s0;
            g_att[(size_t)w * 8 + g + 4] = s1;
            atomicMax(&smax, f2ord(fmaxf(s0, s1)));
        }
    }
    __syncthreads();
    if (threadIdx.x == 0) atomicMax(&g_maxbits, smax);
}

__global__ void scale_kernel() {
    int b = g_maxbits;
    float mx = __int_as_float(b >= 0 ? b : (b ^ 0x7FFFFFFF));
    g_scale = 3.0f / mx;
}

__global__ __launch_bounds__(256)
void edge_exp(const int* __restrict__ recv, int m)
{
    int tid = blockIdx.x * blockDim.x + threadIdx.x;
    if (tid >= m * 8) return;
    int e = tid >> 3;
    int h = tid & 7;
    float a = expf(g_att[tid] * g_scale);
    g_att[tid] = a;
    atomicAdd(&g_sums[(size_t)recv[e] * 8 + h], a);
}

__device__ __forceinline__ void red_add_v4(float* p, float4 v) {
    asm volatile("red.global.add.v4.f32 [%0], {%1,%2,%3,%4};"
                 :: "l"(p), "f"(v.x), "f"(v.y), "f"(v.z), "f"(v.w) : "memory");
}

__global__ __launch_bounds__(256)
void edge_msg(const int* __restrict__ recv, const int* __restrict__ send, int m)
{
    const int w = (blockIdx.x * blockDim.x + threadIdx.x) >> 5;
    const int lane = threadIdx.x & 31;
    if (w >= m) return;
    const int r = recv[w];
    const int s = send[w];
    float wv = 0.f;
    if (lane < 8) {
        float a = g_att[(size_t)w * 8 + lane];
        float d = g_sums[(size_t)r * 8 + lane];
        wv = a / (d * 5.656854249492381f);
    }
    const float4* V4 = (const float4*)(g_V + (size_t)s * 256);
    float*        Ar = g_agg + (size_t)r * 256;

    float w0 = __shfl_sync(0xffffffffu, wv, lane >> 3);
    float w1 = __shfl_sync(0xffffffffu, wv, (lane + 32) >> 3);
    float4 v0 = V4[lane];
    float4 v1 = V4[lane + 32];
    v0.x *= w0; v0.y *= w0; v0.z *= w0; v0.w *= w0;
    v1.x *= w1; v1.y *= w1; v1.z *= w1; v1.w *= w1;
    red_add_v4(Ar + lane * 4, v0);
    red_add_v4(Ar + (lane + 32) * 4, v1);
}

// ---------------- launch ----------------
extern "C" void kernel_launch(void* const* d_in, const int* in_sizes, int n_in,
                              void* d_out, int out_size)
{
    const float* x    = (const float*)d_in[0];
    const int*   ei   = (const int*)d_in[1];
    const float* Wk   = (const float*)d_in[2];
    const float* bk   = (const float*)d_in[3];
    const float* Wq   = (const float*)d_in[4];
    const float* bq   = (const float*)d_in[5];
    const float* Wv   = (const float*)d_in[6];
    const float* bv   = (const float*)d_in[7];
    const float* Wagg = (const float*)d_in[8];
    const float* bagg = (const float*)d_in[9];
    const float* Wff  = (const float*)d_in[10];
    const float* bff  = (const float*)d_in[11];
    float* out = (float*)d_out;

    const int n = in_sizes[0] / 256;
    const int m = in_sizes[1] / 2;
    const int* recv = ei;
    const int* send = ei + m;

    float *Qp, *Kp, *Vp, *aggp, *h1p;
    cudaGetSymbolAddress((void**)&Qp,   g_Q);
    cudaGetSymbolAddress((void**)&Kp,   g_K);
    cudaGetSymbolAddress((void**)&Vp,   g_V);
    cudaGetSymbolAddress((void**)&aggp, g_agg);
    cudaGetSymbolAddress((void**)&h1p,  g_h1);

    const int n4_agg  = n * 64;
    const int n4_sums = n * 2;
    init_kernel<<<(n4_agg + 255) / 256, 256>>>(n4_agg, n4_sums);

    const int gx = (n + 127) / 128;

    // fused Q/K/V projections (grid.z picks weight set)
    GemmSet sq = {Wq, bq, Qp};
    GemmSet sk = {Wk, bk, Kp};
    GemmSet sv = {Wv, bv, Vp};
    gemm_tc<false, false, false><<<dim3(gx, 2, 3), 256>>>(x, sq, sk, sv, nullptr, n);

    edge_qk<<<(m + 7) / 8, 256>>>(recv, send, m);
    scale_kernel<<<1, 1>>>();
    edge_exp<<<(m * 8 + 255) / 256, 256>>>(recv, m);
    edge_msg<<<(m + 7) / 8, 256>>>(recv, send, m);

    GemmSet sa = {Wagg, bagg, h1p};
    gemm_tc<true, true, false><<<dim3(gx, 2, 1), 256>>>(aggp, sa, sa, sa, nullptr, n);
    GemmSet sf = {Wff, bff, out};
    gemm_tc<false, true, true><<<dim3(gx, 2, 1), 256>>>(h1p, sf, sf, sf, x, n);
}